// round 2
// baseline (speedup 1.0000x reference)
#include <cuda_runtime.h>

// Problem constants (fixed by the reference)
#define SEQ   1024
#define BSZ   16
#define DIM   1024
#define SIDE  32
#define WPB   32            // warps per block = d-channels per block
#define RCH   4             // rows staged per chunk
#define NCH   (SIDE / RCH)  // 8 chunks

// out[s,b,d] = silu( conv2d_causal(x, K_d)[s] + x[s,b,d]*omega[d] )
// computed by running the 2-state 2D SSM recurrence directly on x
// (equivalent to convolving with its impulse response).
__global__ __launch_bounds__(1024) void ssm2d_kernel(
    const float* __restrict__ x,
    const float* __restrict__ A1, const float* __restrict__ A2,
    const float* __restrict__ B1, const float* __restrict__ B2,
    const float* __restrict__ C1, const float* __restrict__ C2,
    const float* __restrict__ omega,
    float* __restrict__ out)
{
    // [r][j][w] padded to 33 on last dim: loader writes consecutive ldd (conflict
    // free), compute reads stride-33 across lanes j (banks (j+w)%32, conflict free).
    __shared__ float buf[RCH][SIDE][WPB + 1];

    const int lane = threadIdx.x;   // column j (compute role)
    const int w    = threadIdx.y;   // warp id == d within block
    const int b    = blockIdx.y;
    const int d0   = blockIdx.x * WPB;
    const int d    = d0 + w;

    // loader role: linear tid -> (row-col lj, channel ldd), ldd fastest => coalesced
    const int tid = w * 32 + lane;
    const int ldd = tid & 31;
    const int lj  = tid >> 5;

    const float SC = 0.70710678118654752440f;  // sqrt(1/2)

    // per-channel parameters (all lanes of warp w load the same d -> broadcast)
    const float a1_0 = 0.5f / (1.f + __expf(-A1[d * 2 + 0]));
    const float a1_1 = 0.5f / (1.f + __expf(-A1[d * 2 + 1]));
    const float a2_0 = 0.5f / (1.f + __expf(-A2[d * 2 + 0]));
    const float a2_1 = 0.5f / (1.f + __expf(-A2[d * 2 + 1]));
    const float b1_0 = 0.5f / (1.f + __expf(-B1[d * 2 + 0]));
    const float b1_1 = 0.5f / (1.f + __expf(-B1[d * 2 + 1]));
    const float b2_0 = 0.5f / (1.f + __expf(-B2[d * 2 + 0]));
    const float b2_1 = 0.5f / (1.f + __expf(-B2[d * 2 + 1]));
    const float c1_0 = C1[d * 2 + 0] * SC;
    const float c1_1 = C1[d * 2 + 1] * SC;
    const float c2_0 = C2[d * 2 + 0] * SC;
    const float c2_1 = C2[d * 2 + 1] * SC;
    const float om   = omega[d];

    // previous-row state at this column, both state components
    float h0 = 0.f, v0 = 0.f, h1 = 0.f, v1 = 0.f;

    const int base = b * DIM + d0 + ldd;   // gmem base for loader role

    for (int c = 0; c < NCH; ++c) {
        // ---- stage RCH rows of x for all 32 channels (coalesced) ----
        #pragma unroll
        for (int r = 0; r < RCH; ++r) {
            int s = (c * RCH + r) * SIDE + lj;
            buf[r][lj][ldd] = x[s * (BSZ * DIM) + base];
        }
        __syncthreads();

        // ---- recurrence: each warp sweeps its channel, lane = column ----
        #pragma unroll
        for (int r = 0; r < RCH; ++r) {
            float xv = buf[r][lane][w];

            // vertical update (elementwise per column)
            float nv0 = fmaf(a2_0, h0, fmaf(a1_0, v0, b2_0 * xv));
            float nv1 = fmaf(a2_1, h1, fmaf(a1_1, v1, b2_1 * xv));

            // v of previous column in the current row
            float vl0 = __shfl_up_sync(0xffffffffu, nv0, 1);
            float vl1 = __shfl_up_sync(0xffffffffu, nv1, 1);
            if (lane == 0) { vl0 = 0.f; vl1 = 0.f; }

            // horizontal recurrence h_j = a1*h_{j-1} + (a2*v_{j-1} + b1*x_j)
            // via Kogge-Stone scan with coefficient powers a1^{1,2,4,8,16}
            float y0 = fmaf(a2_0, vl0, b1_0 * xv);
            float y1 = fmaf(a2_1, vl1, b1_1 * xv);
            float p0 = a1_0, p1 = a1_1;
            #pragma unroll
            for (int sft = 1; sft < 32; sft <<= 1) {
                float t0 = __shfl_up_sync(0xffffffffu, y0, sft);
                float t1 = __shfl_up_sync(0xffffffffu, y1, sft);
                if (lane >= sft) {
                    y0 = fmaf(p0, t0, y0);
                    y1 = fmaf(p1, t1, y1);
                }
                p0 *= p0; p1 *= p1;
            }
            h0 = y0; h1 = y1; v0 = nv0; v1 = nv1;

            // output projection + residual + silu
            float oc = fmaf(c1_0, h0, fmaf(c2_0, v0, fmaf(c1_1, h1, c2_1 * v1)));
            float yv = fmaf(xv, om, oc);
            float sig = 1.f / (1.f + __expf(-yv));
            buf[r][lane][w] = yv * sig;   // same cell this thread read -> safe
        }
        __syncthreads();

        // ---- write back (coalesced) ----
        #pragma unroll
        for (int r = 0; r < RCH; ++r) {
            int s = (c * RCH + r) * SIDE + lj;
            out[s * (BSZ * DIM) + base] = buf[r][lj][ldd];
        }
        __syncthreads();
    }
}

extern "C" void kernel_launch(void* const* d_in, const int* in_sizes, int n_in,
                              void* d_out, int out_size)
{
    const float* x     = (const float*)d_in[0];
    const float* A1    = (const float*)d_in[1];
    const float* A2    = (const float*)d_in[2];
    const float* B1    = (const float*)d_in[3];
    const float* B2    = (const float*)d_in[4];
    const float* C1    = (const float*)d_in[5];
    const float* C2    = (const float*)d_in[6];
    const float* omega = (const float*)d_in[7];
    float* out = (float*)d_out;

    dim3 block(32, 32);
    dim3 grid(DIM / WPB, BSZ);   // 32 x 16 = 512 blocks
    ssm2d_kernel<<<grid, block>>>(x, A1, A2, B1, B2, C1, C2, omega, out);
}

// round 3
// speedup vs baseline: 1.6978x; 1.6978x over previous
#include <cuda_runtime.h>

// Problem constants (fixed by the reference)
#define SEQ   1024
#define BSZ   16
#define DIM   1024
#define SIDE  32
#define BD    (BSZ * DIM)      // 16384 floats between consecutive seq positions

#define DPB   8                // d-channels per block = warps per block
#define IPB   4                // images (batch entries) per block / per warp
#define RCH   8                // rows staged per chunk
#define NCH   (SIDE / RCH)     // 4 chunks
#define LDD   132              // padded floats per (row, d) stripe: 4*32 + 4 pad

// out[s,b,d] = silu( conv2d_causal(x, K_d)[s] + x[s,b,d]*omega[d] )
// computed by running the 2-state 2D SSM recurrence directly on x.
// Warp = one channel d, 4 images; lane owns 4 contiguous columns of one image.
// Horizontal recurrence: serial-in-lane + 3-step coefficient scan over 8 lanes.
__global__ __launch_bounds__(256, 4) void ssm2d_kernel(
    const float* __restrict__ x,
    const float* __restrict__ A1, const float* __restrict__ A2,
    const float* __restrict__ B1, const float* __restrict__ B2,
    const float* __restrict__ C1, const float* __restrict__ C2,
    const float* __restrict__ omega,
    float* __restrict__ out)
{
    __shared__ __align__(16) float buf[RCH][DPB][LDD];

    const int tid  = threadIdx.x;
    const int w    = tid >> 5;          // warp id == channel within block
    const int lane = tid & 31;
    const int ib   = lane >> 3;         // image index within warp (0..3)
    const int g    = lane & 7;          // column-chunk index (cols 4g..4g+3)

    const int d0 = blockIdx.x * DPB;
    const int b0 = blockIdx.y * IPB;
    const int d  = d0 + w;

    // loader role: tid -> (dd fastest for 32B-sector gmem access, then col)
    const int ldd_ = tid & 7;           // channel 0..7
    const int lcol = tid >> 3;          // column 0..31
    const int gcol_base = b0 * DIM + d0 + ldd_;

    const float SC = 0.70710678118654752440f;  // sqrt(1/2)

    // per-channel parameters (broadcast within warp)
    float a1[2], a2[2], b1[2], b2[2], c1[2], c2[2];
#pragma unroll
    for (int k = 0; k < 2; ++k) {
        a1[k] = 0.5f / (1.f + __expf(-A1[d * 2 + k]));
        a2[k] = 0.5f / (1.f + __expf(-A2[d * 2 + k]));
        b1[k] = 0.5f / (1.f + __expf(-B1[d * 2 + k]));
        b2[k] = 0.5f / (1.f + __expf(-B2[d * 2 + k]));
        c1[k] = C1[d * 2 + k] * SC;
        c2[k] = C2[d * 2 + k] * SC;
    }
    const float om = omega[d];

    // precomputed coefficient powers (constants for scan & reconstruction)
    float p2[2], p3[2], p4[2], A2p[2], A4p[2];
#pragma unroll
    for (int k = 0; k < 2; ++k) {
        p2[k]  = a1[k] * a1[k];
        p3[k]  = p2[k] * a1[k];
        p4[k]  = p2[k] * p2[k];
        A2p[k] = p4[k] * p4[k];     // a1^8
        A4p[k] = A2p[k] * A2p[k];   // a1^16
    }

    // previous-row state for this lane's 4 columns, both components
    float hp[2][4] = {{0.f,0.f,0.f,0.f},{0.f,0.f,0.f,0.f}};
    float vp[2][4] = {{0.f,0.f,0.f,0.f},{0.f,0.f,0.f,0.f}};

    for (int c = 0; c < NCH; ++c) {
        // ---- stage RCH rows x 4 images x 8 channels (32B-sector gmem reads) ----
#pragma unroll
        for (int r = 0; r < RCH; ++r) {
            const int s = (c * RCH + r) * SIDE + lcol;
            const int gb = s * BD + gcol_base;
#pragma unroll
            for (int i = 0; i < IPB; ++i)
                buf[r][ldd_][i * SIDE + lcol] = x[gb + i * DIM];
        }
        __syncthreads();

        // ---- recurrence ----
#pragma unroll
        for (int r = 0; r < RCH; ++r) {
            const float4 xv = *(const float4*)&buf[r][w][ib * SIDE + 4 * g];
            const float xs[4] = {xv.x, xv.y, xv.z, xv.w};

            float acc0 = om * xs[0], acc1 = om * xs[1];
            float acc2 = om * xs[2], acc3 = om * xs[3];

#pragma unroll
            for (int k = 0; k < 2; ++k) {
                // vertical update (elementwise per column)
                float v0 = fmaf(a2[k], hp[k][0], fmaf(a1[k], vp[k][0], b2[k] * xs[0]));
                float v1 = fmaf(a2[k], hp[k][1], fmaf(a1[k], vp[k][1], b2[k] * xs[1]));
                float v2 = fmaf(a2[k], hp[k][2], fmaf(a1[k], vp[k][2], b2[k] * xs[2]));
                float v3 = fmaf(a2[k], hp[k][3], fmaf(a1[k], vp[k][3], b2[k] * xs[3]));

                // v of the column left of this lane's chunk
                float vleft = __shfl_up_sync(0xffffffffu, v3, 1);
                if (g == 0) vleft = 0.f;

                // local serial prefix of h-drive: Y_c = a1*Y_{c-1} + g_c
                float Y0 = fmaf(a2[k], vleft, b1[k] * xs[0]);
                float Y1 = fmaf(a1[k], Y0, fmaf(a2[k], v0, b1[k] * xs[1]));
                float Y2 = fmaf(a1[k], Y1, fmaf(a2[k], v1, b1[k] * xs[2]));
                float Y3 = fmaf(a1[k], Y2, fmaf(a2[k], v2, b1[k] * xs[3]));

                // 3-step scan over 8-lane group, coefficient a1^4 (precomputed powers)
                float S = Y3, t;
                t = __shfl_up_sync(0xffffffffu, S, 1);
                if (g >= 1) S = fmaf(p4[k], t, S);
                t = __shfl_up_sync(0xffffffffu, S, 2);
                if (g >= 2) S = fmaf(A2p[k], t, S);
                t = __shfl_up_sync(0xffffffffu, S, 4);
                if (g >= 4) S = fmaf(A4p[k], t, S);

                // incoming h from left chunk boundary
                float hin = __shfl_up_sync(0xffffffffu, S, 1);
                if (g == 0) hin = 0.f;

                // reconstruct h for the 4 owned columns
                float h0 = fmaf(a1[k], hin, Y0);
                float h1 = fmaf(p2[k], hin, Y1);
                float h2 = fmaf(p3[k], hin, Y2);
                float h3 = fmaf(p4[k], hin, Y3);

                hp[k][0] = h0; hp[k][1] = h1; hp[k][2] = h2; hp[k][3] = h3;
                vp[k][0] = v0; vp[k][1] = v1; vp[k][2] = v2; vp[k][3] = v3;

                acc0 = fmaf(c1[k], h0, fmaf(c2[k], v0, acc0));
                acc1 = fmaf(c1[k], h1, fmaf(c2[k], v1, acc1));
                acc2 = fmaf(c1[k], h2, fmaf(c2[k], v2, acc2));
                acc3 = fmaf(c1[k], h3, fmaf(c2[k], v3, acc3));
            }

            // silu + stage output (same slot this thread read -> no hazard)
            float4 ov;
            ov.x = acc0 * __fdividef(1.f, 1.f + __expf(-acc0));
            ov.y = acc1 * __fdividef(1.f, 1.f + __expf(-acc1));
            ov.z = acc2 * __fdividef(1.f, 1.f + __expf(-acc2));
            ov.w = acc3 * __fdividef(1.f, 1.f + __expf(-acc3));
            *(float4*)&buf[r][w][ib * SIDE + 4 * g] = ov;
        }
        __syncthreads();

        // ---- write back (32B-sector gmem writes) ----
#pragma unroll
        for (int r = 0; r < RCH; ++r) {
            const int s = (c * RCH + r) * SIDE + lcol;
            const int gb = s * BD + gcol_base;
#pragma unroll
            for (int i = 0; i < IPB; ++i)
                out[gb + i * DIM] = buf[r][ldd_][i * SIDE + lcol];
        }
        __syncthreads();
    }
}

extern "C" void kernel_launch(void* const* d_in, const int* in_sizes, int n_in,
                              void* d_out, int out_size)
{
    const float* x     = (const float*)d_in[0];
    const float* A1    = (const float*)d_in[1];
    const float* A2    = (const float*)d_in[2];
    const float* B1    = (const float*)d_in[3];
    const float* B2    = (const float*)d_in[4];
    const float* C1    = (const float*)d_in[5];
    const float* C2    = (const float*)d_in[6];
    const float* omega = (const float*)d_in[7];
    float* out = (float*)d_out;

    dim3 block(DPB * 32);                 // 256 threads
    dim3 grid(DIM / DPB, BSZ / IPB);      // 128 x 4 = 512 blocks
    ssm2d_kernel<<<grid, block>>>(x, A1, A2, B1, B2, C1, C2, omega, out);
}